// round 1
// baseline (speedup 1.0000x reference)
#include <cuda_runtime.h>

#define BB 8
#define TT 512
#define HH 65
#define G4 260
#define VV 32000
#define NROW (BB*TT)          /* 4096 */
#define ZS 68                 /* padded K stride (65 -> 68, zero pad) */

static const long long OUT_MAIN_SIZE = (long long)NROW * VV;  // 131072000

// ---------------- scratch (device globals; no allocation allowed) ----------
__device__ float g_Xg[NROW * G4];    // precomputed x-part of LSTM gates
__device__ float g_enc[NROW * HH];   // LSTM outputs
__device__ float g_q[NROW * HH];     // queries
__device__ float g_son[NROW];
__device__ float g_soff[NROW];
__device__ float g_ctx[NROW * HH];   // attention context
__device__ float g_Z[NROW * ZS];     // pre-projection activations (padded)
__device__ float g_Wp[VV * ZS];      // ov_w padded to ZS

// ---------------- packed fp32x2 FMA (Blackwell FFMA2) ----------------------
union F2U { float2 f; unsigned long long u; };
__device__ __forceinline__ float2 ffma2(float2 a, float2 b, float2 c) {
    F2U A, Bv, C, D;
    A.f = a; Bv.f = b; C.f = c;
    asm("fma.rn.f32x2 %0, %1, %2, %3;" : "=l"(D.u) : "l"(A.u), "l"(Bv.u), "l"(C.u));
    return D.f;
}

// ---------------- pack ov_w into padded layout -----------------------------
__global__ void k_pack(const float* __restrict__ ov_w) {
    int idx = blockIdx.x * blockDim.x + threadIdx.x;
    if (idx >= VV * ZS) return;
    int v = idx / ZS, k = idx - v * ZS;
    g_Wp[idx] = (k < HH) ? ov_w[v * HH + k] : 0.f;
}

// ---------------- embedding + x-part of LSTM gates -------------------------
// Xg[row,g] = b_ih[g] + b_hh[g] + emb[ids[row]] . w_ih[g]
// grid (NROW/16, 2): each block does 16 rows x 130 gates, weights in smem.
__global__ void k_embed(const int* __restrict__ ids, const float* __restrict__ emb,
                        const float* __restrict__ w_ih, const float* __restrict__ b_ih,
                        const float* __restrict__ b_hh) {
    __shared__ float sw[130 * 65];
    __shared__ float er[16 * 65];
    __shared__ float bs[130];
    int row0 = blockIdx.x * 16;
    int g0   = blockIdx.y * 130;
    int tid  = threadIdx.x;
    for (int i = tid; i < 130 * 65; i += 256) sw[i] = w_ih[g0 * 65 + i];
    for (int i = tid; i < 16 * 65; i += 256) {
        int r = i / 65, k = i - r * 65;
        er[i] = emb[ids[row0 + r] * 65 + k];
    }
    if (tid < 130) bs[tid] = b_ih[g0 + tid] + b_hh[g0 + tid];
    __syncthreads();
    for (int o = tid; o < 16 * 130; o += 256) {
        int r = o / 130, g = o - r * 130;
        float acc = bs[g];
        const float* w = sw + g * 65;
        const float* x = er + r * 65;
        #pragma unroll 13
        for (int k = 0; k < 65; k++) acc = fmaf(w[k], x[k], acc);
        g_Xg[(row0 + r) * G4 + g0 + g] = acc;
    }
}

// ---------------- LSTM recurrence (one block per batch) --------------------
__global__ void __launch_bounds__(288, 1)
k_lstm(const float* __restrict__ h0, const float* __restrict__ c0,
       const float* __restrict__ w_hh, float* __restrict__ outH, float* __restrict__ outC) {
    int b = blockIdx.x, tid = threadIdx.x;
    __shared__ __align__(16) float hsf[68];
    __shared__ float cs[65];
    __shared__ float gates[260];

    float2 w2[34];
    if (tid < 260) {
        #pragma unroll
        for (int i = 0; i < 32; i++) {
            w2[i].x = w_hh[tid * 65 + 2 * i];
            w2[i].y = w_hh[tid * 65 + 2 * i + 1];
        }
        w2[32].x = w_hh[tid * 65 + 64]; w2[32].y = 0.f;
        w2[33].x = 0.f; w2[33].y = 0.f;
    }
    if (tid < 65) { hsf[tid] = h0[b * 65 + tid]; cs[tid] = c0[b * 65 + tid]; }
    if (tid >= 65 && tid < 68) hsf[tid] = 0.f;
    __syncthreads();

    for (int t = 0; t < TT; t++) {
        float a = 0.f;
        if (tid < 260) {
            float2 acc0 = make_float2(g_Xg[(b * TT + t) * G4 + tid], 0.f);
            float2 acc1 = make_float2(0.f, 0.f);
            const float4* h4 = (const float4*)hsf;
            #pragma unroll
            for (int i = 0; i < 17; i++) {
                float4 hv = h4[i];
                acc0 = ffma2(w2[2 * i],     make_float2(hv.x, hv.y), acc0);
                acc1 = ffma2(w2[2 * i + 1], make_float2(hv.z, hv.w), acc1);
            }
            float gv = acc0.x + acc0.y + acc1.x + acc1.y;
            // PyTorch gate order i,f,g,o: sigmoid on i,f,o; tanh on g
            a = (tid < 130 || tid >= 195) ? (1.f / (1.f + __expf(-gv))) : tanhf(gv);
        }
        if (tid < 260) gates[tid] = a;
        __syncthreads();
        if (tid < 65) {
            float c = gates[65 + tid] * cs[tid] + gates[tid] * gates[130 + tid];
            cs[tid] = c;
            float h = gates[195 + tid] * tanhf(c);
            hsf[tid] = h;
            g_enc[(b * TT + t) * HH + tid] = h;
        }
        __syncthreads();
    }
    if (tid < 65) { outH[b * 65 + tid] = hsf[tid]; outC[b * 65 + tid] = cs[tid]; }
}

// ---------------- queries + attention scores -------------------------------
// per 16 rows: q = enc@u_w^T+u_b ; kq = enc@w_w^T+w_b ;
// s_on = v.tanh(kq+q)+vb ; s_off = v.tanh(kq)+vb
__global__ void k_keys(const float* __restrict__ u_w, const float* __restrict__ u_b,
                       const float* __restrict__ w_w, const float* __restrict__ w_b,
                       const float* __restrict__ v_w, const float* __restrict__ v_b) {
    __shared__ float swu[65 * 65];
    __shared__ float sww[65 * 65];
    __shared__ float senc[16 * 65];
    __shared__ float sq[16 * 65];
    __shared__ float son_sh[16], soff_sh[16];
    int row0 = blockIdx.x * 16, tid = threadIdx.x;
    for (int i = tid; i < 65 * 65; i += 256) { swu[i] = u_w[i]; sww[i] = w_w[i]; }
    for (int i = tid; i < 16 * 65; i += 256) senc[i] = g_enc[row0 * 65 + i];
    if (tid < 16) { son_sh[tid] = v_b[0]; soff_sh[tid] = v_b[0]; }
    __syncthreads();
    for (int o = tid; o < 16 * 65; o += 256) {
        int r = o / 65, j = o - r * 65;
        float acc = u_b[j];
        const float* w = swu + j * 65;
        const float* x = senc + r * 65;
        #pragma unroll 13
        for (int k = 0; k < 65; k++) acc = fmaf(w[k], x[k], acc);
        sq[o] = acc;
        g_q[(row0 + r) * 65 + j] = acc;
    }
    __syncthreads();
    for (int o = tid; o < 16 * 65; o += 256) {
        int r = o / 65, j = o - r * 65;
        float acc = w_b[j];
        const float* w = sww + j * 65;
        const float* x = senc + r * 65;
        #pragma unroll 13
        for (int k = 0; k < 65; k++) acc = fmaf(w[k], x[k], acc);
        float vj = v_w[j];
        atomicAdd(&son_sh[r],  vj * tanhf(acc + sq[o]));
        atomicAdd(&soff_sh[r], vj * tanhf(acc));
    }
    __syncthreads();
    if (tid < 16) { g_son[row0 + tid] = son_sh[tid]; g_soff[row0 + tid] = soff_sh[tid]; }
}

// ---------------- attention via prefix sums (one block per batch) ----------
// ctx[i,h] = (Pon_i[h] + Soff_tot[h] - Poff_i[h]) / (CumOn_i + TotOff - CumOff_i)
__global__ void __launch_bounds__(288, 1) k_attn() {
    int b = blockIdx.x, tid = threadIdx.x;
    __shared__ float eon[512], eoff[512], con[512], coff[512], invD[512];
    __shared__ float ssn[4][72], ssf[4][72];
    __shared__ float offon[16], offoff[16];
    __shared__ float red[288];
    __shared__ float Msh, totoff_sh;
    const float* son  = g_son  + b * TT;
    const float* soff = g_soff + b * TT;

    float m = -1e30f;
    for (int j = tid; j < TT; j += 288) m = fmaxf(m, fmaxf(son[j], soff[j]));
    red[tid] = m;
    __syncthreads();
    if (tid == 0) { float mm = red[0]; for (int i = 1; i < 288; i++) mm = fmaxf(mm, red[i]); Msh = mm; }
    __syncthreads();
    float M = Msh;
    for (int j = tid; j < TT; j += 288) { eon[j] = __expf(son[j] - M); eoff[j] = __expf(soff[j] - M); }
    __syncthreads();
    if (tid < 16) {
        float s = 0; int base = tid * 32;
        for (int k = 0; k < 32; k++) { s += eon[base + k]; con[base + k] = s; }
    } else if (tid < 32) {
        float s = 0; int base = (tid - 16) * 32;
        for (int k = 0; k < 32; k++) { s += eoff[base + k]; coff[base + k] = s; }
    }
    __syncthreads();
    if (tid == 0) { float s = 0; for (int c = 0; c < 16; c++) { offon[c] = s;  s += con[c * 32 + 31]; } }
    if (tid == 1) { float s = 0; for (int c = 0; c < 16; c++) { offoff[c] = s; s += coff[c * 32 + 31]; } }
    __syncthreads();
    for (int j = tid; j < TT; j += 288) { con[j] += offon[j >> 5]; coff[j] += offoff[j >> 5]; }
    __syncthreads();
    if (tid == 0) totoff_sh = coff[511];
    __syncthreads();
    float totoff = totoff_sh;
    for (int i = tid; i < TT; i += 288) invD[i] = 1.f / (con[i] + totoff - coff[i]);
    __syncthreads();

    int c = tid / 72, h = tid - c * 72;   // 4 chunks x 72 (65 active) = 288
    const float* qb = g_q + b * TT * 65;
    if (h < 65) {
        int j0 = c * 128;
        float sn = 0, sf = 0;
        for (int j = j0; j < j0 + 128; j++) {
            float qv = qb[j * 65 + h];
            sn = fmaf(eon[j], qv, sn);
            sf = fmaf(eoff[j], qv, sf);
        }
        ssn[c][h] = sn; ssf[c][h] = sf;
    }
    __syncthreads();
    if (h < 65) {
        float pon = 0, poff = 0, Sh = 0;
        #pragma unroll
        for (int cc = 0; cc < 4; cc++) {
            Sh += ssf[cc][h];
            if (cc < c) { pon += ssn[cc][h]; poff += ssf[cc][h]; }
        }
        int j0 = c * 128;
        float* ctxb = g_ctx + b * TT * 65;
        for (int j = j0; j < j0 + 128; j++) {
            float qv = qb[j * 65 + h];
            pon  = fmaf(eon[j],  qv, pon);
            poff = fmaf(eoff[j], qv, poff);
            ctxb[j * 65 + h] = (pon + Sh - poff) * invD[j];
        }
    }
}

// ---------------- Z = enc@oh^T + ctx@oz^T + biases (padded) ----------------
__global__ void k_zmix(const float* __restrict__ oh_w, const float* __restrict__ oh_b,
                       const float* __restrict__ oz_w, const float* __restrict__ oz_b) {
    __shared__ float swh[65 * 65], swz[65 * 65];
    __shared__ float senc[16 * 65], sctx[16 * 65];
    int row0 = blockIdx.x * 16, tid = threadIdx.x;
    for (int i = tid; i < 65 * 65; i += 256) { swh[i] = oh_w[i]; swz[i] = oz_w[i]; }
    for (int i = tid; i < 16 * 65; i += 256) { senc[i] = g_enc[row0 * 65 + i]; sctx[i] = g_ctx[row0 * 65 + i]; }
    __syncthreads();
    for (int o = tid; o < 16 * 65; o += 256) {
        int r = o / 65, j = o - r * 65;
        float acc = oh_b[j] + oz_b[j];
        const float* wh = swh + j * 65;
        const float* wz = swz + j * 65;
        const float* xe = senc + r * 65;
        const float* xc = sctx + r * 65;
        #pragma unroll 13
        for (int k = 0; k < 65; k++) {
            acc = fmaf(wh[k], xe[k], acc);
            acc = fmaf(wz[k], xc[k], acc);
        }
        g_Z[(row0 + r) * ZS + j] = acc;
    }
    for (int o = tid; o < 16 * 3; o += 256) {
        int r = o / 3, p = o - r * 3;
        g_Z[(row0 + r) * ZS + 65 + p] = 0.f;
    }
}

// ---------------- output projection: out = Z @ Wp^T + ov_b -----------------
// block = 8 rows x 256 vocab, thread = 1 vocab x 8 rows; f32x2-packed along K.
__global__ void __launch_bounds__(256) k_gemm(const float* __restrict__ ov_b,
                                              float* __restrict__ out) {
    __shared__ __align__(16) float zt[8 * ZS];
    int row0 = blockIdx.y * 8;
    int v = blockIdx.x * 256 + threadIdx.x;
    for (int i = threadIdx.x; i < 8 * ZS; i += 256) zt[i] = g_Z[row0 * ZS + i];
    __syncthreads();

    const float4* w4 = (const float4*)(g_Wp + (long long)v * ZS);
    float2 acc[8];
    #pragma unroll
    for (int r = 0; r < 8; r++) acc[r] = make_float2(0.f, 0.f);

    #pragma unroll
    for (int i = 0; i < ZS / 4; i++) {    // 17 iterations of K=4
        float4 wv = w4[i];
        float2 wa = make_float2(wv.x, wv.y);
        float2 wb = make_float2(wv.z, wv.w);
        #pragma unroll
        for (int r = 0; r < 8; r++) {
            float4 zv = ((const float4*)(zt + r * ZS))[i];
            acc[r] = ffma2(wa, make_float2(zv.x, zv.y), acc[r]);
            acc[r] = ffma2(wb, make_float2(zv.z, zv.w), acc[r]);
        }
    }
    float bias = ov_b[v];
    float* o = out + (long long)row0 * VV + v;
    #pragma unroll
    for (int r = 0; r < 8; r++) o[(long long)r * VV] = acc[r].x + acc[r].y + bias;
}

// ---------------------------------------------------------------------------
extern "C" void kernel_launch(void* const* d_in, const int* in_sizes, int n_in,
                              void* d_out, int out_size) {
    const int*   ids  = (const int*)  d_in[0];
    const float* h0   = (const float*)d_in[1];
    const float* c0   = (const float*)d_in[2];
    const float* emb  = (const float*)d_in[3];
    const float* w_ih = (const float*)d_in[4];
    const float* w_hh = (const float*)d_in[5];
    const float* b_ih = (const float*)d_in[6];
    const float* b_hh = (const float*)d_in[7];
    const float* u_w  = (const float*)d_in[8];
    const float* u_b  = (const float*)d_in[9];
    const float* w_w  = (const float*)d_in[10];
    const float* w_b  = (const float*)d_in[11];
    const float* v_w  = (const float*)d_in[12];
    const float* v_b  = (const float*)d_in[13];
    const float* oz_w = (const float*)d_in[14];
    const float* oz_b = (const float*)d_in[15];
    const float* oh_w = (const float*)d_in[16];
    const float* oh_b = (const float*)d_in[17];
    const float* ov_w = (const float*)d_in[18];
    const float* ov_b = (const float*)d_in[19];

    float* out  = (float*)d_out;
    float* outH = out + OUT_MAIN_SIZE;
    float* outC = outH + BB * HH;

    k_pack<<<(VV * ZS + 255) / 256, 256>>>(ov_w);
    k_embed<<<dim3(NROW / 16, 2), 256>>>(ids, emb, w_ih, b_ih, b_hh);
    k_lstm<<<BB, 288>>>(h0, c0, w_hh, outH, outC);
    k_keys<<<NROW / 16, 256>>>(u_w, u_b, w_w, w_b, v_w, v_b);
    k_attn<<<BB, 288>>>();
    k_zmix<<<NROW / 16, 256>>>(oh_w, oh_b, oz_w, oz_b);
    k_gemm<<<dim3(VV / 256, NROW / 8), 256>>>(ov_b, out);
}